// round 15
// baseline (speedup 1.0000x reference)
#include <cuda_runtime.h>
#include <cuda_fp16.h>
#include <math.h>
#include <stdint.h>

#define Dm   1024
#define Vm   32000
#define Hm   16
#define DHm  64
#define Bm   32
#define Sm   100
#define Mm   3200          // B*S
#define FFm  4096
#define Lm   2
#define LN_EPS 1e-5f
#define Q_EPS  1e-6f

// ---------------- scratch (static device globals; no allocation) -------------
__device__ float g_h  [Mm * Dm];
__device__ float g_tmp[Mm * Dm];
__device__ float g_qkv[Mm * 3 * Dm];
__device__ __half g_ah[Mm * Dm];           // activation fp16 (h or ctx)
__device__ __half g_fh[Mm * FFm];          // ff fp16
__device__ __half g_wh[FFm * Dm];          // weight fp16 (max 4096x1024)
__device__ __half g_twq[(size_t)Vm * Dm];  // ternary decoder weights (exact fp16)
__device__ float g_partial[1024];
__device__ float g_gval;

// ---------------- small helpers ----------------------------------------------
__device__ __forceinline__ uint32_t smem_u32(const void* p) {
    uint32_t a;
    asm("{ .reg .u64 t; cvta.to.shared.u64 t, %1; cvt.u32.u64 %0, t; }" : "=r"(a) : "l"(p));
    return a;
}

__device__ __forceinline__ float gelu_exact(float x) {
    return 0.5f * x * (1.0f + erff(x * 0.70710678118654752440f));
}

// e^x for x <= 0 (softmax use), FMA-only (no MUFU), rel err ~7e-7
__device__ __forceinline__ float fast_exp(float x) {
    float p = x * 1.4426950408889634f;      // log2(e)
    p = fmaxf(p, -126.0f);
    float fl = floorf(p);
    float f = p - fl;                        // [0,1)
    float r = 1.52527338e-5f;
    r = fmaf(r, f, 1.54035304e-4f);
    r = fmaf(r, f, 1.33335581e-3f);
    r = fmaf(r, f, 9.61812911e-3f);
    r = fmaf(r, f, 5.55041087e-2f);
    r = fmaf(r, f, 2.40226507e-1f);
    r = fmaf(r, f, 6.93147181e-1f);
    r = fmaf(r, f, 1.0f);
    int i = (int)fl;
    float sc = __int_as_float((i + 127) << 23);
    return r * sc;
}

__device__ __forceinline__ float block_reduce_sum(float v) {
    __shared__ float red[32];
    int lane = threadIdx.x & 31;
    int wid  = threadIdx.x >> 5;
#pragma unroll
    for (int o = 16; o > 0; o >>= 1) v += __shfl_xor_sync(0xffffffffu, v, o);
    if (lane == 0) red[wid] = v;
    __syncthreads();
    int nw = blockDim.x >> 5;
    float s = (threadIdx.x < nw) ? red[threadIdx.x] : 0.f;
    if (wid == 0) {
#pragma unroll
        for (int o = 16; o > 0; o >>= 1) s += __shfl_xor_sync(0xffffffffu, s, o);
        if (lane == 0) red[0] = s;
    }
    __syncthreads();
    float r = red[0];
    __syncthreads();
    return r;
}

// ---------------- elementwise kernels -----------------------------------------
__global__ void embed_kernel(const int* __restrict__ x,
                             const float* __restrict__ embed,
                             const float* __restrict__ pos,
                             __half* __restrict__ hi) {
    int i = blockIdx.x * blockDim.x + threadIdx.x;
    if (i >= Mm * Dm) return;
    int m = i / Dm, d = i - m * Dm;
    int s = m % Sm;
    float v = embed[(size_t)x[m] * Dm + d] + pos[s * Dm + d];
    g_h[i] = v;
    hi[i] = __float2half_rn(v);
}

// fp32 -> fp16 convert (weights)
__global__ void convert_kernel(const float* __restrict__ src,
                               __half* __restrict__ dst, int n) {
    int i = blockIdx.x * blockDim.x + threadIdx.x;
    if (i >= n) return;
    dst[i] = __float2half_rn(src[i]);
}

// ---------------- mma.sync GEMM (round-6 core, 5-stage pipeline) ---------------
// C[M,N] = sum_seg A_s[M,K] * B_s[N,K]^T + bias (opt GELU, opt fp32 out, opt fp16 out)
// CTA tile 128x128, BK=32, 128 threads (4 warps 2x2), warp tile 64x64, 2 CTAs/SM.

#define BMt 128
#define BNt 128
#define NTHREADS 128
#define SROW 40                    // halves per smem row (32 data + 8 pad)
#define STAGES 5
#define A_STAGE (BMt * SROW)       // halves
#define B_STAGE (BNt * SROW)
#define GEMM_SMEM_BYTES ((STAGES * (A_STAGE + B_STAGE)) * 2)   // 102400

__device__ __forceinline__ void cp_async16(uint32_t dst, const void* src) {
    asm volatile("cp.async.cg.shared.global [%0], [%1], 16;" :: "r"(dst), "l"(src));
}
__device__ __forceinline__ void ldsm_x4(uint32_t* r, uint32_t addr) {
    asm volatile("ldmatrix.sync.aligned.m8n8.x4.shared.b16 {%0,%1,%2,%3}, [%4];"
                 : "=r"(r[0]), "=r"(r[1]), "=r"(r[2]), "=r"(r[3]) : "r"(addr));
}
__device__ __forceinline__ void mma_16816(float* d, const uint32_t* a, uint32_t b0, uint32_t b1) {
    asm volatile(
        "mma.sync.aligned.m16n8k16.row.col.f32.f16.f16.f32 "
        "{%0,%1,%2,%3}, {%4,%5,%6,%7}, {%8,%9}, {%0,%1,%2,%3};"
        : "+f"(d[0]), "+f"(d[1]), "+f"(d[2]), "+f"(d[3])
        : "r"(a[0]), "r"(a[1]), "r"(a[2]), "r"(a[3]), "r"(b0), "r"(b1));
}

#define PREFETCH(it, buf)                                                        \
    {                                                                            \
        int seg_ = (it) / tilesPerSeg;                                           \
        int k0_  = ((it) - seg_ * tilesPerSeg) << 5;                             \
        const __half* Ap_ = As[seg_] + (size_t)(mt * BMt) * K + k0_;             \
        const __half* Bp_ = Bs[seg_] + (size_t)(nt * BNt) * K + k0_;             \
        __half* dA_ = sA + (buf) * A_STAGE;                                      \
        __half* dB_ = sB + (buf) * B_STAGE;                                      \
        _Pragma("unroll")                                                        \
        for (int j_ = 0; j_ < 4; j_++) {                                         \
            int c_ = tid + NTHREADS * j_;                                        \
            int row_ = c_ >> 2, ch_ = (c_ & 3) * 8;                              \
            cp_async16(smem_u32(dA_ + row_ * SROW + ch_),                        \
                       Ap_ + (size_t)row_ * K + ch_);                            \
        }                                                                        \
        _Pragma("unroll")                                                        \
        for (int j_ = 0; j_ < 4; j_++) {                                         \
            int c_ = tid + NTHREADS * j_;                                        \
            int row_ = c_ >> 2, ch_ = (c_ & 3) * 8;                              \
            cp_async16(smem_u32(dB_ + row_ * SROW + ch_),                        \
                       Bp_ + (size_t)row_ * K + ch_);                            \
        }                                                                        \
    }

template<bool GELU, bool F32OUT, bool H16OUT>
__global__ __launch_bounds__(NTHREADS, 2) void gemm_mma(
    const __half* __restrict__ A0, const __half* __restrict__ A1,
    const __half* __restrict__ A2,
    const __half* __restrict__ B0, const __half* __restrict__ B1,
    const __half* __restrict__ B2,
    int nseg, const float* __restrict__ bias, float* __restrict__ C,
    __half* __restrict__ Hi,
    int N, int K)
{
    extern __shared__ __align__(16) __half smem[];
    __half* sA = smem;                       // [STAGES][A_STAGE]
    __half* sB = smem + STAGES * A_STAGE;    // [STAGES][B_STAGE]

    const int tid = threadIdx.x;
    const int wid = tid >> 5;
    const int lane = tid & 31;
    const int warp_m = wid & 1;        // 0..1 (64 rows each)
    const int warp_n = wid >> 1;       // 0..1 (64 cols each)
    const int mt = blockIdx.x;
    const int nt = blockIdx.y;

    const __half* As[3] = {A0, A1, A2};
    const __half* Bs[3] = {B0, B1, B2};
    const int tilesPerSeg = K >> 5;          // K/32
    const int T = nseg * tilesPerSeg;

    float acc[4][8][4];
#pragma unroll
    for (int i = 0; i < 4; i++)
#pragma unroll
        for (int j = 0; j < 8; j++)
#pragma unroll
            for (int r = 0; r < 4; r++) acc[i][j][r] = 0.f;

    // ldmatrix lane addressing
    const int q = lane >> 3, lr = lane & 7;
    const int a_row_base = warp_m * 64 + (q & 1) * 8 + lr;   // + mi*16
    const int a_kq = (q >> 1) * 8;
    const int b_row_base = warp_n * 64 + (q >> 1) * 8 + lr;  // + jp*16
    const int b_kq = (q & 1) * 8;

    PREFETCH(0, 0);
    asm volatile("cp.async.commit_group;" ::: "memory");
    PREFETCH(1, 1);
    asm volatile("cp.async.commit_group;" ::: "memory");
    PREFETCH(2, 2);
    asm volatile("cp.async.commit_group;" ::: "memory");
    PREFETCH(3, 3);
    asm volatile("cp.async.commit_group;" ::: "memory");

    for (int it = 0; it < T; it++) {
        asm volatile("cp.async.wait_group %0;" :: "n"(STAGES - 2) : "memory");
        __syncthreads();

        const int pf = it + STAGES - 1;
        if (pf < T) { PREFETCH(pf, pf % STAGES); }
        asm volatile("cp.async.commit_group;" ::: "memory");

        const __half* sAb = sA + (it % STAGES) * A_STAGE;
        const __half* sBb = sB + (it % STAGES) * B_STAGE;
#pragma unroll
        for (int ks = 0; ks < 2; ks++) {
            uint32_t a[4][4];
#pragma unroll
            for (int mi = 0; mi < 4; mi++)
                ldsm_x4(a[mi], smem_u32(&sAb[(a_row_base + mi * 16) * SROW + ks * 16 + a_kq]));
            uint32_t b[4][4];
#pragma unroll
            for (int jp = 0; jp < 4; jp++)
                ldsm_x4(b[jp], smem_u32(&sBb[(b_row_base + jp * 16) * SROW + ks * 16 + b_kq]));
#pragma unroll
            for (int mi = 0; mi < 4; mi++)
#pragma unroll
                for (int nj = 0; nj < 8; nj++) {
                    int jp = nj >> 1, h = nj & 1;
                    mma_16816(acc[mi][nj], a[mi], b[jp][h * 2], b[jp][h * 2 + 1]);
                }
        }
    }

    // epilogue
    const int g  = lane >> 2;
    const int tg = lane & 3;
#pragma unroll
    for (int mi = 0; mi < 4; mi++) {
#pragma unroll
        for (int nj = 0; nj < 8; nj++) {
            int row = mt * BMt + warp_m * 64 + mi * 16 + g;
            int col = nt * BNt + warp_n * 64 + nj * 8 + tg * 2;
            float b0 = bias[col], b1 = bias[col + 1];
            float v0 = acc[mi][nj][0] + b0;
            float v1 = acc[mi][nj][1] + b1;
            float v2 = acc[mi][nj][2] + b0;
            float v3 = acc[mi][nj][3] + b1;
            if (GELU) { v0 = gelu_exact(v0); v1 = gelu_exact(v1);
                        v2 = gelu_exact(v2); v3 = gelu_exact(v3); }
            size_t i0 = (size_t)row * N + col;
            size_t i1 = (size_t)(row + 8) * N + col;
            if (F32OUT) {
                *(float2*)(C + i0) = make_float2(v0, v1);
                *(float2*)(C + i1) = make_float2(v2, v3);
            }
            if (H16OUT) {
                *(__half2*)(Hi + i0) = __halves2half2(__float2half_rn(v0), __float2half_rn(v1));
                *(__half2*)(Hi + i1) = __halves2half2(__float2half_rn(v2), __float2half_rn(v3));
            }
        }
    }
}

// ---------------- fused attention: split-q, 4 blocks/SM, MUFU-free -----------
// Each block handles 50 q-rows of one (b,h). K/V full, Q half. 54KB smem.
#define DHS2 34                    // half2 elements per row (32 data + 2 pad)
#define QH 50                      // q rows per block
#define ATTN_THREADS 256
#define ATTN_SMEM ((2 * Sm + QH) * DHS2 * 4 + QH * Sm * 4 + 64 * 4)   // 54456 B

__global__ __launch_bounds__(ATTN_THREADS) void attn_kernel(const float* __restrict__ qkv,
                                                            __half* __restrict__ chi) {
    extern __shared__ __align__(16) char asmem_raw[];
    __half2* Ks = (__half2*)asmem_raw;               // [Sm][DHS2]
    __half2* Vs = Ks + Sm * DHS2;                    // [Sm][DHS2]
    __half2* Qs = Vs + Sm * DHS2;                    // [QH][DHS2]
    float*   P  = (float*)(Qs + QH * DHS2);          // [QH][Sm]
    float* sInv = P + QH * Sm;                        // [QH]

    const int h = blockIdx.x % Hm;
    const int b = blockIdx.x / Hm;
    const int base = b * Sm;
    const int q0 = blockIdx.y * QH;
    const int tid = threadIdx.x;

    // phase 0: cooperative K/V (full) + Q (half) load
    for (int idx = tid; idx < Sm * (DHm / 4); idx += ATTN_THREADS) {
        int r = idx >> 4, c4 = (idx & 15) * 4;
        const float* row = qkv + (size_t)(base + r) * (3 * Dm) + h * DHm + c4;
        float4 kv = *(const float4*)(row + Dm);
        float4 vv = *(const float4*)(row + 2 * Dm);
        int o = r * DHS2 + (c4 >> 1);
        Ks[o]     = __floats2half2_rn(kv.x, kv.y);
        Ks[o + 1] = __floats2half2_rn(kv.z, kv.w);
        Vs[o]     = __floats2half2_rn(vv.x, vv.y);
        Vs[o + 1] = __floats2half2_rn(vv.z, vv.w);
        int rq = r - q0;
        if (rq >= 0 && rq < QH) {
            float4 qv = *(const float4*)(row);
            int oq = rq * DHS2 + (c4 >> 1);
            Qs[oq]     = __floats2half2_rn(qv.x, qv.y);
            Qs[oq + 1] = __floats2half2_rn(qv.z, qv.w);
        }
    }
    __syncthreads();

    // phase 1: S = Q K^T * 0.125  (16x16 thread grid, 4x7 register tiles)
    {
        const int qt = tid >> 4, kt = tid & 15;   // qt*4 over 64>=50, kt*7 over 112>=100
        float acc[4][7];
#pragma unroll
        for (int i = 0; i < 4; i++)
#pragma unroll
            for (int j = 0; j < 7; j++) acc[i][j] = 0.f;

        for (int d2 = 0; d2 < DHm / 2; d2++) {
            float2 qr[4], kr[7];
#pragma unroll
            for (int i = 0; i < 4; i++) {
                int qq = qt * 4 + i; qq = qq < QH ? qq : QH - 1;
                qr[i] = __half22float2(Qs[qq * DHS2 + d2]);
            }
#pragma unroll
            for (int j = 0; j < 7; j++) {
                int kk = kt * 7 + j; kk = kk < Sm ? kk : Sm - 1;
                kr[j] = __half22float2(Ks[kk * DHS2 + d2]);
            }
#pragma unroll
            for (int i = 0; i < 4; i++)
#pragma unroll
                for (int j = 0; j < 7; j++) {
                    acc[i][j] = fmaf(qr[i].x, kr[j].x, acc[i][j]);
                    acc[i][j] = fmaf(qr[i].y, kr[j].y, acc[i][j]);
                }
        }
#pragma unroll
        for (int i = 0; i < 4; i++) {
            int qq = qt * 4 + i;
            if (qq < QH) {
#pragma unroll
                for (int j = 0; j < 7; j++) {
                    int kk = kt * 7 + j;
                    if (kk < Sm) P[qq * Sm + kk] = acc[i][j] * 0.125f;
                }
            }
        }
    }
    __syncthreads();

    // phase 2: row softmax, FMA-only exp
    if (tid < QH) {
        float* Pr = P + tid * Sm;
        float mx = -1e30f;
        for (int k = 0; k < Sm; k++) mx = fmaxf(mx, Pr[k]);
        float sum = 0.f;
        for (int k = 0; k < Sm; k++) {
            float e = fast_exp(Pr[k] - mx);
            Pr[k] = e;
            sum += e;
        }
        sInv[tid] = 1.f / sum;
    }
    __syncthreads();

    // phase 3: ctx = P . V  (thread (qt,dt): 4 q-rows x 4 d-cols)
    {
        const int qt = tid >> 4, dt = tid & 15;
        float acc[4][4];
#pragma unroll
        for (int i = 0; i < 4; i++)
#pragma unroll
            for (int j = 0; j < 4; j++) acc[i][j] = 0.f;

        for (int k = 0; k < Sm; k++) {
            float2 v0 = __half22float2(Vs[k * DHS2 + dt * 2]);
            float2 v1 = __half22float2(Vs[k * DHS2 + dt * 2 + 1]);
            float pr[4];
#pragma unroll
            for (int i = 0; i < 4; i++) {
                int qq = qt * 4 + i; qq = qq < QH ? qq : QH - 1;
                pr[i] = P[qq * Sm + k];
            }
#pragma unroll
            for (int i = 0; i < 4; i++) {
                acc[i][0] = fmaf(pr[i], v0.x, acc[i][0]);
                acc[i][1] = fmaf(pr[i], v0.y, acc[i][1]);
                acc[i][2] = fmaf(pr[i], v1.x, acc[i][2]);
                acc[i][3] = fmaf(pr[i], v1.y, acc[i][3]);
            }
        }
#pragma unroll
        for (int i = 0; i < 4; i++) {
            int qq = qt * 4 + i;
            if (qq < QH) {
                float inv = sInv[qq];
                size_t co = (size_t)(base + q0 + qq) * Dm + h * DHm + dt * 4;
                *(__half2*)(chi + co) = __halves2half2(
                    __float2half_rn(acc[i][0] * inv), __float2half_rn(acc[i][1] * inv));
                *(__half2*)(chi + co + 2) = __halves2half2(
                    __float2half_rn(acc[i][2] * inv), __float2half_rn(acc[i][3] * inv));
            }
        }
    }
}

// ---------------- residual + layernorm (in place on g_h, emits fp16) ---------
__global__ __launch_bounds__(256) void ln_kernel(float* __restrict__ h,
                                                 const float* __restrict__ delta,
                                                 const float* __restrict__ w,
                                                 const float* __restrict__ bias,
                                                 __half* __restrict__ hi) {
    const int row = blockIdx.x;
    const size_t off = (size_t)row * Dm;
    float v[4];
    float s = 0.f;
#pragma unroll
    for (int i = 0; i < 4; i++) {
        int c = threadIdx.x + i * 256;
        v[i] = h[off + c] + delta[off + c];
        s += v[i];
    }
    float mean = block_reduce_sum(s) * (1.f / Dm);
    float s2 = 0.f;
#pragma unroll
    for (int i = 0; i < 4; i++) { float d = v[i] - mean; s2 += d * d; }
    float var = block_reduce_sum(s2) * (1.f / Dm);
    float inv = rsqrtf(var + LN_EPS);
#pragma unroll
    for (int i = 0; i < 4; i++) {
        int c = threadIdx.x + i * 256;
        float o = (v[i] - mean) * inv * w[c] + bias[c];
        h[off + c] = o;
        hi[off + c] = __float2half_rn(o);
    }
}

// ---------------- decoder weight scale + quantize ----------------------------
__global__ __launch_bounds__(256) void absum_kernel(const float* __restrict__ w) {
    float s = 0.f;
    const size_t total = (size_t)Vm * Dm;
    for (size_t i = (size_t)blockIdx.x * blockDim.x + threadIdx.x; i < total;
         i += (size_t)gridDim.x * blockDim.x)
        s += fabsf(w[i]);
    float bs = block_reduce_sum(s);
    if (threadIdx.x == 0) g_partial[blockIdx.x] = bs;
}

__global__ __launch_bounds__(256) void finalize_g_kernel() {
    float s = 0.f;
    for (int i = threadIdx.x; i < 1024; i += 256) s += g_partial[i];
    float t = block_reduce_sum(s);
    if (threadIdx.x == 0) g_gval = t / (float)((size_t)Vm * Dm);
}

__global__ void quant_kernel(const float* __restrict__ w) {
    size_t i = (size_t)blockIdx.x * blockDim.x + threadIdx.x;
    if (i >= (size_t)Vm * Dm) return;
    float inv = 1.f / (g_gval + Q_EPS);
    float t = rintf(w[i] * inv);             // round-half-to-even == jnp.round
    g_twq[i] = __float2half_rn(fminf(1.f, fmaxf(-1.f, t)));  // exact: -1/0/1
}

// ---------------- host orchestration -----------------------------------------
extern "C" void kernel_launch(void* const* d_in, const int* in_sizes, int n_in,
                              void* d_out, int out_size) {
    const int*   x     = (const int*)  d_in[0];
    const float* embed = (const float*)d_in[1];
    const float* pos   = (const float*)d_in[2];
    const float* Wqkv  = (const float*)d_in[3];
    const float* bqkv  = (const float*)d_in[4];
    const float* Wo    = (const float*)d_in[5];
    const float* bo    = (const float*)d_in[6];
    const float* ln1w  = (const float*)d_in[7];
    const float* ln1b  = (const float*)d_in[8];
    const float* W1    = (const float*)d_in[9];
    const float* b1    = (const float*)d_in[10];
    const float* W2    = (const float*)d_in[11];
    const float* b2    = (const float*)d_in[12];
    const float* ln2w  = (const float*)d_in[13];
    const float* ln2b  = (const float*)d_in[14];
    const float* decw  = (const float*)d_in[15];
    const float* decb  = (const float*)d_in[16];
    float* out = (float*)d_out;

    float *h, *tmp, *qkv;
    __half *ah, *fh, *wh, *twq;
    cudaGetSymbolAddress((void**)&h,   g_h);
    cudaGetSymbolAddress((void**)&tmp, g_tmp);
    cudaGetSymbolAddress((void**)&qkv, g_qkv);
    cudaGetSymbolAddress((void**)&ah,  g_ah);
    cudaGetSymbolAddress((void**)&fh,  g_fh);
    cudaGetSymbolAddress((void**)&wh,  g_wh);
    cudaGetSymbolAddress((void**)&twq, g_twq);

    cudaFuncSetAttribute(gemm_mma<false, true, false>,
                         cudaFuncAttributeMaxDynamicSharedMemorySize, GEMM_SMEM_BYTES);
    cudaFuncSetAttribute(gemm_mma<true, false, true>,
                         cudaFuncAttributeMaxDynamicSharedMemorySize, GEMM_SMEM_BYTES);
    cudaFuncSetAttribute(attn_kernel,
                         cudaFuncAttributeMaxDynamicSharedMemorySize, ATTN_SMEM);

    // 1. embedding + positional (writes h + fp16)
    embed_kernel<<<(Mm * Dm + 255) / 256, 256>>>(x, embed, pos, ah);

    // 2. encoder layers — single-pass fp16 GEMMs (Ah * Bh)
    for (int l = 0; l < Lm; l++) {
        const float* Wqkv_l = Wqkv + (size_t)l * 3 * Dm * Dm;
        const float* bqkv_l = bqkv + (size_t)l * 3 * Dm;
        const float* Wo_l   = Wo   + (size_t)l * Dm * Dm;
        const float* bo_l   = bo   + (size_t)l * Dm;
        const float* W1_l   = W1   + (size_t)l * FFm * Dm;
        const float* b1_l   = b1   + (size_t)l * FFm;
        const float* W2_l   = W2   + (size_t)l * Dm * FFm;
        const float* b2_l   = b2   + (size_t)l * Dm;

        // qkv = h @ Wqkv^T + bqkv      [3200, 3072]  (f32 out)
        convert_kernel<<<(3 * Dm * Dm + 255) / 256, 256>>>(Wqkv_l, wh, 3 * Dm * Dm);
        gemm_mma<false, true, false><<<dim3(Mm / BMt, 3 * Dm / BNt), NTHREADS, GEMM_SMEM_BYTES>>>(
            ah, (const __half*)0, (const __half*)0, wh, (const __half*)0, (const __half*)0,
            1, bqkv_l, qkv, (__half*)0, 3 * Dm, Dm);

        // attention (f32 qkv) -> ctx fp16 (overwrites ah); split-q grid
        attn_kernel<<<dim3(Bm * Hm, 2), ATTN_THREADS, ATTN_SMEM>>>(qkv, ah);

        // attn_out = ctx @ Wo^T + bo   (f32 out -> tmp)
        convert_kernel<<<(Dm * Dm + 255) / 256, 256>>>(Wo_l, wh, Dm * Dm);
        gemm_mma<false, true, false><<<dim3(Mm / BMt, Dm / BNt), NTHREADS, GEMM_SMEM_BYTES>>>(
            ah, (const __half*)0, (const __half*)0, wh, (const __half*)0, (const __half*)0,
            1, bo_l, tmp, (__half*)0, Dm, Dm);

        // h = LN(h + attn_out)  (writes h + ah)
        ln_kernel<<<Mm, 256>>>(h, tmp, ln1w + (size_t)l * Dm, ln1b + (size_t)l * Dm, ah);

        // ff = gelu(h @ W1^T + b1)     [3200, 4096]  (fp16 out -> fh)
        convert_kernel<<<(FFm * Dm + 255) / 256, 256>>>(W1_l, wh, FFm * Dm);
        gemm_mma<true, false, true><<<dim3(Mm / BMt, FFm / BNt), NTHREADS, GEMM_SMEM_BYTES>>>(
            ah, (const __half*)0, (const __half*)0, wh, (const __half*)0, (const __half*)0,
            1, b1_l, (float*)0, fh, FFm, Dm);

        // ff2 = ff @ W2^T + b2         [3200, 1024], K = 4096  (f32 out -> tmp)
        convert_kernel<<<(Dm * FFm + 255) / 256, 256>>>(W2_l, wh, Dm * FFm);
        gemm_mma<false, true, false><<<dim3(Mm / BMt, Dm / BNt), NTHREADS, GEMM_SMEM_BYTES>>>(
            fh, (const __half*)0, (const __half*)0, wh, (const __half*)0, (const __half*)0,
            1, b2_l, tmp, (__half*)0, Dm, FFm);

        // h = LN(h + ff2)  (writes h + ah; last layer's ah feeds decoder)
        ln_kernel<<<Mm, 256>>>(h, tmp, ln2w + (size_t)l * Dm, ln2b + (size_t)l * Dm, ah);
    }

    // 3. ternary decoder
    absum_kernel<<<1024, 256>>>(decw);
    finalize_g_kernel<<<1, 256>>>();
    quant_kernel<<<(int)(((size_t)Vm * Dm + 255) / 256), 256>>>(decw);

    // out = h @ tw^T + dec_b           [3200, 32000]  single fp16 pass
    gemm_mma<false, true, false><<<dim3(Mm / BMt, Vm / BNt), NTHREADS, GEMM_SMEM_BYTES>>>(
        ah, (const __half*)0, (const __half*)0, twq, (const __half*)0, (const __half*)0,
        1, decb, out, (__half*)0, Vm, Dm);
}

// round 16
// speedup vs baseline: 1.0569x; 1.0569x over previous
#include <cuda_runtime.h>
#include <cuda_fp16.h>
#include <math.h>
#include <stdint.h>

#define Dm   1024
#define Vm   32000
#define Hm   16
#define DHm  64
#define Bm   32
#define Sm   100
#define Mm   3200          // B*S
#define FFm  4096
#define Lm   2
#define LN_EPS 1e-5f
#define Q_EPS  1e-6f

// ---------------- scratch (static device globals; no allocation) -------------
__device__ float g_h  [Mm * Dm];
__device__ float g_tmp[Mm * Dm];
__device__ float g_qkv[Mm * 3 * Dm];
__device__ __half g_ah[Mm * Dm];           // activation fp16 (h or ctx)
__device__ __half g_fh[Mm * FFm];          // ff fp16
__device__ __half g_wqkv16[Lm * 3 * Dm * Dm];   // all-layer fp16 weights
__device__ __half g_wo16  [Lm * Dm * Dm];
__device__ __half g_w116  [Lm * FFm * Dm];
__device__ __half g_w216  [Lm * Dm * FFm];
__device__ __half g_twq[(size_t)Vm * Dm];  // ternary decoder weights (exact fp16)
__device__ float g_partial[1024];
__device__ float g_gval;

// ---------------- small helpers ----------------------------------------------
__device__ __forceinline__ uint32_t smem_u32(const void* p) {
    uint32_t a;
    asm("{ .reg .u64 t; cvta.to.shared.u64 t, %1; cvt.u32.u64 %0, t; }" : "=r"(a) : "l"(p));
    return a;
}

__device__ __forceinline__ float gelu_exact(float x) {
    return 0.5f * x * (1.0f + erff(x * 0.70710678118654752440f));
}

// e^x for x <= 0 (softmax use), FMA-only (no MUFU), rel err ~7e-7
__device__ __forceinline__ float fast_exp(float x) {
    float p = x * 1.4426950408889634f;      // log2(e)
    p = fmaxf(p, -126.0f);
    float fl = floorf(p);
    float f = p - fl;                        // [0,1)
    float r = 1.52527338e-5f;
    r = fmaf(r, f, 1.54035304e-4f);
    r = fmaf(r, f, 1.33335581e-3f);
    r = fmaf(r, f, 9.61812911e-3f);
    r = fmaf(r, f, 5.55041087e-2f);
    r = fmaf(r, f, 2.40226507e-1f);
    r = fmaf(r, f, 6.93147181e-1f);
    r = fmaf(r, f, 1.0f);
    int i = (int)fl;
    float sc = __int_as_float((i + 127) << 23);
    return r * sc;
}

__device__ __forceinline__ float block_reduce_sum(float v) {
    __shared__ float red[32];
    int lane = threadIdx.x & 31;
    int wid  = threadIdx.x >> 5;
#pragma unroll
    for (int o = 16; o > 0; o >>= 1) v += __shfl_xor_sync(0xffffffffu, v, o);
    if (lane == 0) red[wid] = v;
    __syncthreads();
    int nw = blockDim.x >> 5;
    float s = (threadIdx.x < nw) ? red[threadIdx.x] : 0.f;
    if (wid == 0) {
#pragma unroll
        for (int o = 16; o > 0; o >>= 1) s += __shfl_xor_sync(0xffffffffu, s, o);
        if (lane == 0) red[0] = s;
    }
    __syncthreads();
    float r = red[0];
    __syncthreads();
    return r;
}

// ---------------- elementwise kernels -----------------------------------------
__global__ void embed_kernel(const int* __restrict__ x,
                             const float* __restrict__ embed,
                             const float* __restrict__ pos,
                             __half* __restrict__ hi) {
    int i = blockIdx.x * blockDim.x + threadIdx.x;
    if (i >= Mm * Dm) return;
    int m = i / Dm, d = i - m * Dm;
    int s = m % Sm;
    float v = embed[(size_t)x[m] * Dm + d] + pos[s * Dm + d];
    g_h[i] = v;
    hi[i] = __float2half_rn(v);
}

// fp32 -> fp16 convert (weights; vectorized)
__global__ void convert_kernel(const float* __restrict__ src,
                               __half* __restrict__ dst, int n4) {
    int i = blockIdx.x * blockDim.x + threadIdx.x;
    if (i >= n4) return;
    float4 v = ((const float4*)src)[i];
    __half2 a = __halves2half2(__float2half_rn(v.x), __float2half_rn(v.y));
    __half2 b = __halves2half2(__float2half_rn(v.z), __float2half_rn(v.w));
    ((__half2*)dst)[i * 2]     = a;
    ((__half2*)dst)[i * 2 + 1] = b;
}

// ---------------- mma.sync GEMM (round-6-proven core, 4 stages) ----------------
// C[M,N] = sum_seg A_s[M,K] * B_s[N,K]^T + bias (opt GELU, opt fp32 out, opt fp16 out)
// CTA tile 128x128, BK=32, 128 threads (4 warps 2x2), warp tile 64x64, 2 CTAs/SM.

#define BMt 128
#define BNt 128
#define NTHREADS 128
#define SROW 40                    // halves per smem row (32 data + 8 pad)
#define STAGES 4
#define A_STAGE (BMt * SROW)       // halves
#define B_STAGE (BNt * SROW)
#define GEMM_SMEM_BYTES ((STAGES * (A_STAGE + B_STAGE)) * 2)   // 81920

__device__ __forceinline__ void cp_async16(uint32_t dst, const void* src) {
    asm volatile("cp.async.cg.shared.global [%0], [%1], 16;" :: "r"(dst), "l"(src));
}
__device__ __forceinline__ void ldsm_x4(uint32_t* r, uint32_t addr) {
    asm volatile("ldmatrix.sync.aligned.m8n8.x4.shared.b16 {%0,%1,%2,%3}, [%4];"
                 : "=r"(r[0]), "=r"(r[1]), "=r"(r[2]), "=r"(r[3]) : "r"(addr));
}
__device__ __forceinline__ void mma_16816(float* d, const uint32_t* a, uint32_t b0, uint32_t b1) {
    asm volatile(
        "mma.sync.aligned.m16n8k16.row.col.f32.f16.f16.f32 "
        "{%0,%1,%2,%3}, {%4,%5,%6,%7}, {%8,%9}, {%0,%1,%2,%3};"
        : "+f"(d[0]), "+f"(d[1]), "+f"(d[2]), "+f"(d[3])
        : "r"(a[0]), "r"(a[1]), "r"(a[2]), "r"(a[3]), "r"(b0), "r"(b1));
}

#define PREFETCH(it, buf)                                                        \
    {                                                                            \
        int seg_ = (it) / tilesPerSeg;                                           \
        int k0_  = ((it) - seg_ * tilesPerSeg) << 5;                             \
        const __half* Ap_ = As[seg_] + (size_t)(mt * BMt) * K + k0_;             \
        const __half* Bp_ = Bs[seg_] + (size_t)(nt * BNt) * K + k0_;             \
        __half* dA_ = sA + (buf) * A_STAGE;                                      \
        __half* dB_ = sB + (buf) * B_STAGE;                                      \
        _Pragma("unroll")                                                        \
        for (int j_ = 0; j_ < 4; j_++) {                                         \
            int c_ = tid + NTHREADS * j_;                                        \
            int row_ = c_ >> 2, ch_ = (c_ & 3) * 8;                              \
            cp_async16(smem_u32(dA_ + row_ * SROW + ch_),                        \
                       Ap_ + (size_t)row_ * K + ch_);                            \
        }                                                                        \
        _Pragma("unroll")                                                        \
        for (int j_ = 0; j_ < 4; j_++) {                                         \
            int c_ = tid + NTHREADS * j_;                                        \
            int row_ = c_ >> 2, ch_ = (c_ & 3) * 8;                              \
            cp_async16(smem_u32(dB_ + row_ * SROW + ch_),                        \
                       Bp_ + (size_t)row_ * K + ch_);                            \
        }                                                                        \
    }

template<bool GELU, bool F32OUT, bool H16OUT>
__global__ __launch_bounds__(NTHREADS, 2) void gemm_mma(
    const __half* __restrict__ A0, const __half* __restrict__ A1,
    const __half* __restrict__ A2,
    const __half* __restrict__ B0, const __half* __restrict__ B1,
    const __half* __restrict__ B2,
    int nseg, const float* __restrict__ bias, float* __restrict__ C,
    __half* __restrict__ Hi,
    int N, int K)
{
    extern __shared__ __align__(16) __half smem[];
    __half* sA = smem;                       // [STAGES][A_STAGE]
    __half* sB = smem + STAGES * A_STAGE;    // [STAGES][B_STAGE]

    const int tid = threadIdx.x;
    const int wid = tid >> 5;
    const int lane = tid & 31;
    const int warp_m = wid & 1;        // 0..1 (64 rows each)
    const int warp_n = wid >> 1;       // 0..1 (64 cols each)
    const int mt = blockIdx.x;
    const int nt = blockIdx.y;

    const __half* As[3] = {A0, A1, A2};
    const __half* Bs[3] = {B0, B1, B2};
    const int tilesPerSeg = K >> 5;          // K/32
    const int T = nseg * tilesPerSeg;

    float acc[4][8][4];
#pragma unroll
    for (int i = 0; i < 4; i++)
#pragma unroll
        for (int j = 0; j < 8; j++)
#pragma unroll
            for (int r = 0; r < 4; r++) acc[i][j][r] = 0.f;

    // ldmatrix lane addressing
    const int q = lane >> 3, lr = lane & 7;
    const int a_row_base = warp_m * 64 + (q & 1) * 8 + lr;   // + mi*16
    const int a_kq = (q >> 1) * 8;
    const int b_row_base = warp_n * 64 + (q >> 1) * 8 + lr;  // + jp*16
    const int b_kq = (q & 1) * 8;

    PREFETCH(0, 0);
    asm volatile("cp.async.commit_group;" ::: "memory");
    PREFETCH(1, 1);
    asm volatile("cp.async.commit_group;" ::: "memory");
    PREFETCH(2, 2);
    asm volatile("cp.async.commit_group;" ::: "memory");

    for (int it = 0; it < T; it++) {
        asm volatile("cp.async.wait_group %0;" :: "n"(STAGES - 2) : "memory");
        __syncthreads();

        const int pf = it + STAGES - 1;
        if (pf < T) { PREFETCH(pf, pf % STAGES); }
        asm volatile("cp.async.commit_group;" ::: "memory");

        const __half* sAb = sA + (it % STAGES) * A_STAGE;
        const __half* sBb = sB + (it % STAGES) * B_STAGE;
#pragma unroll
        for (int ks = 0; ks < 2; ks++) {
            uint32_t a[4][4];
#pragma unroll
            for (int mi = 0; mi < 4; mi++)
                ldsm_x4(a[mi], smem_u32(&sAb[(a_row_base + mi * 16) * SROW + ks * 16 + a_kq]));
            uint32_t b[4][4];
#pragma unroll
            for (int jp = 0; jp < 4; jp++)
                ldsm_x4(b[jp], smem_u32(&sBb[(b_row_base + jp * 16) * SROW + ks * 16 + b_kq]));
#pragma unroll
            for (int mi = 0; mi < 4; mi++)
#pragma unroll
                for (int nj = 0; nj < 8; nj++) {
                    int jp = nj >> 1, h = nj & 1;
                    mma_16816(acc[mi][nj], a[mi], b[jp][h * 2], b[jp][h * 2 + 1]);
                }
        }
    }

    // epilogue
    const int g  = lane >> 2;
    const int tg = lane & 3;
#pragma unroll
    for (int mi = 0; mi < 4; mi++) {
#pragma unroll
        for (int nj = 0; nj < 8; nj++) {
            int row = mt * BMt + warp_m * 64 + mi * 16 + g;
            int col = nt * BNt + warp_n * 64 + nj * 8 + tg * 2;
            float b0 = bias[col], b1 = bias[col + 1];
            float v0 = acc[mi][nj][0] + b0;
            float v1 = acc[mi][nj][1] + b1;
            float v2 = acc[mi][nj][2] + b0;
            float v3 = acc[mi][nj][3] + b1;
            if (GELU) { v0 = gelu_exact(v0); v1 = gelu_exact(v1);
                        v2 = gelu_exact(v2); v3 = gelu_exact(v3); }
            size_t i0 = (size_t)row * N + col;
            size_t i1 = (size_t)(row + 8) * N + col;
            if (F32OUT) {
                *(float2*)(C + i0) = make_float2(v0, v1);
                *(float2*)(C + i1) = make_float2(v2, v3);
            }
            if (H16OUT) {
                *(__half2*)(Hi + i0) = __halves2half2(__float2half_rn(v0), __float2half_rn(v1));
                *(__half2*)(Hi + i1) = __halves2half2(__float2half_rn(v2), __float2half_rn(v3));
            }
        }
    }
}

// ---------------- fused attention (round-11-proven): f32 qkv in, fp16 ctx out -
// Q/K/V stored as half2 in smem (81KB -> 2 CTAs/SM). P stays fp32.
#define DHS2 34                    // half2 elements per row (32 data + 2 pad)
#define ATTN_THREADS 256
#define ATTN_SMEM (3 * Sm * DHS2 * 4 + Sm * Sm * 4 + 128 * 4)   // 81312 B

__global__ __launch_bounds__(ATTN_THREADS) void attn_kernel(const float* __restrict__ qkv,
                                                            __half* __restrict__ chi) {
    extern __shared__ __align__(16) char asmem_raw[];
    __half2* Qs = (__half2*)asmem_raw;               // [Sm][DHS2]
    __half2* Ks = Qs + Sm * DHS2;
    __half2* Vs = Ks + Sm * DHS2;
    float*   P  = (float*)(Vs + Sm * DHS2);          // [Sm][Sm]
    float* sInv = P + Sm * Sm;                        // [Sm]

    const int h = blockIdx.x % Hm;
    const int b = blockIdx.x / Hm;
    const int base = b * Sm;
    const int tid = threadIdx.x;

    // phase 0: cooperative Q/K/V load (float4 -> 2x half2)
    for (int idx = tid; idx < Sm * (DHm / 4); idx += ATTN_THREADS) {
        int r = idx >> 4, c4 = (idx & 15) * 4;
        const float* row = qkv + (size_t)(base + r) * (3 * Dm) + h * DHm + c4;
        float4 qv = *(const float4*)(row);
        float4 kv = *(const float4*)(row + Dm);
        float4 vv = *(const float4*)(row + 2 * Dm);
        int o = r * DHS2 + (c4 >> 1);
        Qs[o]     = __floats2half2_rn(qv.x, qv.y);
        Qs[o + 1] = __floats2half2_rn(qv.z, qv.w);
        Ks[o]     = __floats2half2_rn(kv.x, kv.y);
        Ks[o + 1] = __floats2half2_rn(kv.z, kv.w);
        Vs[o]     = __floats2half2_rn(vv.x, vv.y);
        Vs[o + 1] = __floats2half2_rn(vv.z, vv.w);
    }
    __syncthreads();

    // phase 1: S = Q K^T * 0.125  (16x16 thread grid, 7x7 register tiles)
    {
        const int qt = tid >> 4, kt = tid & 15;
        float acc[7][7];
#pragma unroll
        for (int i = 0; i < 7; i++)
#pragma unroll
            for (int j = 0; j < 7; j++) acc[i][j] = 0.f;

        for (int d2 = 0; d2 < DHm / 2; d2++) {
            float2 qr[7], kr[7];
#pragma unroll
            for (int i = 0; i < 7; i++) {
                int qq = qt * 7 + i; qq = qq < Sm ? qq : Sm - 1;
                int kk = kt * 7 + i; kk = kk < Sm ? kk : Sm - 1;
                qr[i] = __half22float2(Qs[qq * DHS2 + d2]);
                kr[i] = __half22float2(Ks[kk * DHS2 + d2]);
            }
#pragma unroll
            for (int i = 0; i < 7; i++)
#pragma unroll
                for (int j = 0; j < 7; j++) {
                    acc[i][j] = fmaf(qr[i].x, kr[j].x, acc[i][j]);
                    acc[i][j] = fmaf(qr[i].y, kr[j].y, acc[i][j]);
                }
        }
#pragma unroll
        for (int i = 0; i < 7; i++) {
            int qq = qt * 7 + i;
            if (qq < Sm) {
#pragma unroll
                for (int j = 0; j < 7; j++) {
                    int kk = kt * 7 + j;
                    if (kk < Sm) P[qq * Sm + kk] = acc[i][j] * 0.125f;
                }
            }
        }
    }
    __syncthreads();

    // phase 2: row softmax, FMA-only exp
    if (tid < Sm) {
        float* Pr = P + tid * Sm;
        float mx = -1e30f;
        for (int k = 0; k < Sm; k++) mx = fmaxf(mx, Pr[k]);
        float sum = 0.f;
        for (int k = 0; k < Sm; k++) {
            float e = fast_exp(Pr[k] - mx);
            Pr[k] = e;
            sum += e;
        }
        sInv[tid] = 1.f / sum;
    }
    __syncthreads();

    // phase 3: ctx = P . V  (thread (qt,dt): 7 q-rows x 4 d-cols)
    {
        const int qt = tid >> 4, dt = tid & 15;
        float acc[7][4];
#pragma unroll
        for (int i = 0; i < 7; i++)
#pragma unroll
            for (int j = 0; j < 4; j++) acc[i][j] = 0.f;

        for (int k = 0; k < Sm; k++) {
            float2 v0 = __half22float2(Vs[k * DHS2 + dt * 2]);
            float2 v1 = __half22float2(Vs[k * DHS2 + dt * 2 + 1]);
            float pr[7];
#pragma unroll
            for (int i = 0; i < 7; i++) {
                int qq = qt * 7 + i; qq = qq < Sm ? qq : Sm - 1;
                pr[i] = P[qq * Sm + k];
            }
#pragma unroll
            for (int i = 0; i < 7; i++) {
                acc[i][0] = fmaf(pr[i], v0.x, acc[i][0]);
                acc[i][1] = fmaf(pr[i], v0.y, acc[i][1]);
                acc[i][2] = fmaf(pr[i], v1.x, acc[i][2]);
                acc[i][3] = fmaf(pr[i], v1.y, acc[i][3]);
            }
        }
#pragma unroll
        for (int i = 0; i < 7; i++) {
            int qq = qt * 7 + i;
            if (qq < Sm) {
                float inv = sInv[qq];
                size_t co = (size_t)(base + qq) * Dm + h * DHm + dt * 4;
                *(__half2*)(chi + co) = __halves2half2(
                    __float2half_rn(acc[i][0] * inv), __float2half_rn(acc[i][1] * inv));
                *(__half2*)(chi + co + 2) = __halves2half2(
                    __float2half_rn(acc[i][2] * inv), __float2half_rn(acc[i][3] * inv));
            }
        }
    }
}

// ---------------- residual + layernorm (in place on g_h, emits fp16) ---------
__global__ __launch_bounds__(256) void ln_kernel(float* __restrict__ h,
                                                 const float* __restrict__ delta,
                                                 const float* __restrict__ w,
                                                 const float* __restrict__ bias,
                                                 __half* __restrict__ hi) {
    const int row = blockIdx.x;
    const size_t off = (size_t)row * Dm;
    float v[4];
    float s = 0.f;
#pragma unroll
    for (int i = 0; i < 4; i++) {
        int c = threadIdx.x + i * 256;
        v[i] = h[off + c] + delta[off + c];
        s += v[i];
    }
    float mean = block_reduce_sum(s) * (1.f / Dm);
    float s2 = 0.f;
#pragma unroll
    for (int i = 0; i < 4; i++) { float d = v[i] - mean; s2 += d * d; }
    float var = block_reduce_sum(s2) * (1.f / Dm);
    float inv = rsqrtf(var + LN_EPS);
#pragma unroll
    for (int i = 0; i < 4; i++) {
        int c = threadIdx.x + i * 256;
        float o = (v[i] - mean) * inv * w[c] + bias[c];
        h[off + c] = o;
        hi[off + c] = __float2half_rn(o);
    }
}

// ---------------- decoder weight scale + quantize ----------------------------
__global__ __launch_bounds__(256) void absum_kernel(const float* __restrict__ w) {
    float s = 0.f;
    const size_t total = (size_t)Vm * Dm;
    for (size_t i = (size_t)blockIdx.x * blockDim.x + threadIdx.x; i < total;
         i += (size_t)gridDim.x * blockDim.x)
        s += fabsf(w[i]);
    float bs = block_reduce_sum(s);
    if (threadIdx.x == 0) g_partial[blockIdx.x] = bs;
}

__global__ __launch_bounds__(256) void finalize_g_kernel() {
    float s = 0.f;
    for (int i = threadIdx.x; i < 1024; i += 256) s += g_partial[i];
    float t = block_reduce_sum(s);
    if (threadIdx.x == 0) g_gval = t / (float)((size_t)Vm * Dm);
}

__global__ void quant_kernel(const float* __restrict__ w) {
    size_t i = (size_t)blockIdx.x * blockDim.x + threadIdx.x;
    if (i >= (size_t)Vm * Dm) return;
    float inv = 1.f / (g_gval + Q_EPS);
    float t = rintf(w[i] * inv);             // round-half-to-even == jnp.round
    g_twq[i] = __float2half_rn(fminf(1.f, fmaxf(-1.f, t)));  // exact: -1/0/1
}

// ---------------- host orchestration -----------------------------------------
extern "C" void kernel_launch(void* const* d_in, const int* in_sizes, int n_in,
                              void* d_out, int out_size) {
    const int*   x     = (const int*)  d_in[0];
    const float* embed = (const float*)d_in[1];
    const float* pos   = (const float*)d_in[2];
    const float* Wqkv  = (const float*)d_in[3];
    const float* bqkv  = (const float*)d_in[4];
    const float* Wo    = (const float*)d_in[5];
    const float* bo    = (const float*)d_in[6];
    const float* ln1w  = (const float*)d_in[7];
    const float* ln1b  = (const float*)d_in[8];
    const float* W1    = (const float*)d_in[9];
    const float* b1    = (const float*)d_in[10];
    const float* W2    = (const float*)d_in[11];
    const float* b2    = (const float*)d_in[12];
    const float* ln2w  = (const float*)d_in[13];
    const float* ln2b  = (const float*)d_in[14];
    const float* decw  = (const float*)d_in[15];
    const float* decb  = (const float*)d_in[16];
    float* out = (float*)d_out;

    float *h, *tmp, *qkv;
    __half *ah, *fh, *wqkv16, *wo16, *w116, *w216, *twq;
    cudaGetSymbolAddress((void**)&h,      g_h);
    cudaGetSymbolAddress((void**)&tmp,    g_tmp);
    cudaGetSymbolAddress((void**)&qkv,    g_qkv);
    cudaGetSymbolAddress((void**)&ah,     g_ah);
    cudaGetSymbolAddress((void**)&fh,     g_fh);
    cudaGetSymbolAddress((void**)&wqkv16, g_wqkv16);
    cudaGetSymbolAddress((void**)&wo16,   g_wo16);
    cudaGetSymbolAddress((void**)&w116,   g_w116);
    cudaGetSymbolAddress((void**)&w216,   g_w216);
    cudaGetSymbolAddress((void**)&twq,    g_twq);

    cudaFuncSetAttribute(gemm_mma<false, true, false>,
                         cudaFuncAttributeMaxDynamicSharedMemorySize, GEMM_SMEM_BYTES);
    cudaFuncSetAttribute(gemm_mma<true, false, true>,
                         cudaFuncAttributeMaxDynamicSharedMemorySize, GEMM_SMEM_BYTES);
    cudaFuncSetAttribute(attn_kernel,
                         cudaFuncAttributeMaxDynamicSharedMemorySize, ATTN_SMEM);

    // 0. batched weight conversion (contiguous across layers) + decoder prep
    convert_kernel<<<(Lm * 3 * Dm * Dm / 4 + 255) / 256, 256>>>(Wqkv, wqkv16, Lm * 3 * Dm * Dm / 4);
    convert_kernel<<<(Lm * Dm * Dm / 4 + 255) / 256, 256>>>(Wo, wo16, Lm * Dm * Dm / 4);
    convert_kernel<<<(Lm * FFm * Dm / 4 + 255) / 256, 256>>>(W1, w116, Lm * FFm * Dm / 4);
    convert_kernel<<<(Lm * Dm * FFm / 4 + 255) / 256, 256>>>(W2, w216, Lm * Dm * FFm / 4);
    absum_kernel<<<1024, 256>>>(decw);
    finalize_g_kernel<<<1, 256>>>();
    quant_kernel<<<(int)(((size_t)Vm * Dm + 255) / 256), 256>>>(decw);

    // 1. embedding + positional (writes h + fp16)
    embed_kernel<<<(Mm * Dm + 255) / 256, 256>>>(x, embed, pos, ah);

    // 2. encoder layers — single-pass fp16 GEMMs (Ah * Bh)
    for (int l = 0; l < Lm; l++) {
        const __half* Wqkv_l = wqkv16 + (size_t)l * 3 * Dm * Dm;
        const float*  bqkv_l = bqkv   + (size_t)l * 3 * Dm;
        const __half* Wo_l   = wo16   + (size_t)l * Dm * Dm;
        const float*  bo_l   = bo     + (size_t)l * Dm;
        const __half* W1_l   = w116   + (size_t)l * FFm * Dm;
        const float*  b1_l   = b1     + (size_t)l * FFm;
        const __half* W2_l   = w216   + (size_t)l * Dm * FFm;
        const float*  b2_l   = b2     + (size_t)l * Dm;

        // qkv = h @ Wqkv^T + bqkv      [3200, 3072]  (f32 out)
        gemm_mma<false, true, false><<<dim3(Mm / BMt, 3 * Dm / BNt), NTHREADS, GEMM_SMEM_BYTES>>>(
            ah, (const __half*)0, (const __half*)0, Wqkv_l, (const __half*)0, (const __half*)0,
            1, bqkv_l, qkv, (__half*)0, 3 * Dm, Dm);

        // attention (f32 qkv) -> ctx fp16 (overwrites ah)
        attn_kernel<<<Bm * Hm, ATTN_THREADS, ATTN_SMEM>>>(qkv, ah);

        // attn_out = ctx @ Wo^T + bo   (f32 out -> tmp)
        gemm_mma<false, true, false><<<dim3(Mm / BMt, Dm / BNt), NTHREADS, GEMM_SMEM_BYTES>>>(
            ah, (const __half*)0, (const __half*)0, Wo_l, (const __half*)0, (const __half*)0,
            1, bo_l, tmp, (__half*)0, Dm, Dm);

        // h = LN(h + attn_out)  (writes h + ah)
        ln_kernel<<<Mm, 256>>>(h, tmp, ln1w + (size_t)l * Dm, ln1b + (size_t)l * Dm, ah);

        // ff = gelu(h @ W1^T + b1)     [3200, 4096]  (fp16 out -> fh)
        gemm_mma<true, false, true><<<dim3(Mm / BMt, FFm / BNt), NTHREADS, GEMM_SMEM_BYTES>>>(
            ah, (const __half*)0, (const __half*)0, W1_l, (const __half*)0, (const __half*)0,
            1, b1_l, (float*)0, fh, FFm, Dm);

        // ff2 = ff @ W2^T + b2         [3200, 1024], K = 4096  (f32 out -> tmp)
        gemm_mma<false, true, false><<<dim3(Mm / BMt, Dm / BNt), NTHREADS, GEMM_SMEM_BYTES>>>(
            fh, (const __half*)0, (const __half*)0, W2_l, (const __half*)0, (const __half*)0,
            1, b2_l, tmp, (__half*)0, Dm, FFm);

        // h = LN(h + ff2)  (writes h + ah; last layer's ah feeds decoder)
        ln_kernel<<<Mm, 256>>>(h, tmp, ln2w + (size_t)l * Dm, ln2b + (size_t)l * Dm, ah);
    }

    // 3. out = h @ tw^T + dec_b        [3200, 32000]  single fp16 pass
    gemm_mma<false, true, false><<<dim3(Mm / BMt, Vm / BNt), NTHREADS, GEMM_SMEM_BYTES>>>(
        ah, (const __half*)0, (const __half*)0, twq, (const __half*)0, (const __half*)0,
        1, decb, out, (__half*)0, Vm, Dm);
}